// round 16
// baseline (speedup 1.0000x reference)
#include <cuda_runtime.h>
#include <cuda_fp16.h>

#define BB 4
#define CC 64
#define NN 8192
#define KK 20
#define CO 64
#define BUFSZ 16
#define SEGS 2                 // column halves
#define CNT_TOT (BB * NN * KK)

#define QT 128          // queries per CTA
#define CT 64           // candidates per step
#define STEPS (NN / CT) // 128
#define RS 144          // smem row stride bytes (128B data + 16B pad)

typedef unsigned long long u64;
typedef unsigned int u32;

// ---------------- device scratch ----------------
__device__ float g_sqn[BB * NN];
__device__ __align__(16) u32 g_xhi[BB * NN * 32];   // f16x2 [point][64ch]
__device__ __align__(16) u32 g_xlo[BB * NN * 32];
__device__ float g_y1[BB * NN * CO];
__device__ float g_y3[BB * NN * CO];
__device__ float g_segk[BB * NN * SEGS * KK];
__device__ int   g_segi[BB * NN * SEGS * KK];
__device__ int   g_idx[BB * NN * KK];
__device__ float g_maxh[BB * NN * CO];
__device__ float g_minh[BB * NN * CO];
__device__ float g_sum[CO];
__device__ float g_sumsq[CO];
__device__ float g_scale[CO];
__device__ float g_shift[CO];

__device__ __forceinline__ float finf() { return __int_as_float(0x7f800000); }

// ---------------- smem layout (bytes) ----------------
// S region (128*66*4 = 33792) doubles as A_hi staging (needs 128*144=18432)
#define SM_S    0
#define SM_ALO  33792
#define SM_B    (33792 + 18432)                  // 52224; buffer w at +w*18432 (hi|lo)
#define SM_CSQ  (SM_B + 2 * 18432)               // 89088; buffer w at +w*256
#define SM_BYTES (SM_CSQ + 512)                  // 89600

// ---------------- PTX helpers ----------------
__device__ __forceinline__ u32 smem_u32(const void* p) {
    u32 a;
    asm("{ .reg .u64 t; cvta.to.shared.u64 t, %1; cvt.u32.u64 %0, t; }" : "=r"(a) : "l"(p));
    return a;
}
__device__ __forceinline__ void ldm4(u32& r0, u32& r1, u32& r2, u32& r3, u32 addr) {
    asm volatile("ldmatrix.sync.aligned.m8n8.x4.shared.b16 {%0,%1,%2,%3}, [%4];"
                 : "=r"(r0), "=r"(r1), "=r"(r2), "=r"(r3) : "r"(addr));
}
__device__ __forceinline__ void mma_f16(float (&c)[4], const u32 a0, const u32 a1,
                                        const u32 a2, const u32 a3,
                                        const u32 b0, const u32 b1) {
    asm volatile(
        "mma.sync.aligned.m16n8k16.row.col.f32.f16.f16.f32 "
        "{%0,%1,%2,%3}, {%4,%5,%6,%7}, {%8,%9}, {%0,%1,%2,%3};"
        : "+f"(c[0]), "+f"(c[1]), "+f"(c[2]), "+f"(c[3])
        : "r"(a0), "r"(a1), "r"(a2), "r"(a3), "r"(b0), "r"(b1));
}
__device__ __forceinline__ void cp16(u32 dst, const void* src) {
    asm volatile("cp.async.cg.shared.global [%0], [%1], 16;" :: "r"(dst), "l"(src));
}
__device__ __forceinline__ void cp_commit() { asm volatile("cp.async.commit_group;" ::: "memory"); }
__device__ __forceinline__ void cp_wait0()  { asm volatile("cp.async.wait_group 0;" ::: "memory"); }

// packed f32x2: acc = a*b + acc (in-place, no MOV tax)
__device__ __forceinline__ void fma2(u64& acc, u64 a, u64 b) {
    asm("fma.rn.f32x2 %0, %1, %2, %0;" : "+l"(acc) : "l"(a), "l"(b));
}
__device__ __forceinline__ u64 pack2(float x, float y) {
    u64 r;
    asm("mov.b64 %0, {%1,%2};" : "=l"(r) : "f"(x), "f"(y));
    return r;
}

// ---------------- top-k helpers (registers only; static indices) --------
__device__ __forceinline__ void topk_insert(float (&bk)[KK], int (&bi)[KK],
                                            float& thr, float key, int jg) {
    bool done = false;
#pragma unroll
    for (int t = 0; t < KK; ++t)
        if (!done && bk[t] == thr) { bk[t] = key; bi[t] = jg; done = true; }
    float m = bk[0];
#pragma unroll
    for (int t = 1; t < KK; ++t) m = fmaxf(m, bk[t]);
    thr = m;
}
__device__ __forceinline__ void topk_flush(float (&bk)[KK], int (&bi)[KK], float& thr,
                                           u64* buf, int& cnt) {
#pragma unroll 1
    for (int i = 0; i < cnt; ++i) {
        u64 e = buf[i];
        float kk = __uint_as_float((u32)(e >> 32));
        if (kk < thr) topk_insert(bk, bi, thr, kk, (int)(u32)e);
    }
    cnt = 0;
}

// ---------------- kernel 0 ----------------
__global__ void init_stats_kernel() {
    int o = threadIdx.x;
    g_sum[o] = 0.0f;
    g_sumsq[o] = 0.0f;
}

// ---------------- kernel 1: fp16 hi/lo split + squared norms -------------
__global__ void xhl_kernel(const float* __restrict__ x) {
    int i = blockIdx.x * 256 + threadIdx.x;
    int b = i >> 13;
    const float* xb = x + (size_t)b * CC * NN + (i & (NN - 1));
    u32 uh[32], ul[32];
    float s = 0.0f;
#pragma unroll
    for (int c2 = 0; c2 < 32; ++c2) {
        float v0 = xb[(2 * c2) * NN];
        float v1 = xb[(2 * c2 + 1) * NN];
        s = fmaf(v0, v0, s);
        s = fmaf(v1, v1, s);
        __half h0 = __float2half_rn(v0);
        __half h1 = __float2half_rn(v1);
        __half l0 = __float2half_rn(v0 - __half2float(h0));
        __half l1 = __float2half_rn(v1 - __half2float(h1));
        uh[c2] = (u32)__half_as_ushort(h0) | ((u32)__half_as_ushort(h1) << 16);
        ul[c2] = (u32)__half_as_ushort(l0) | ((u32)__half_as_ushort(l1) << 16);
    }
    g_sqn[i] = s;
    uint4* dh = (uint4*)(g_xhi + (size_t)i * 32);
    uint4* dl = (uint4*)(g_xlo + (size_t)i * 32);
#pragma unroll
    for (int j = 0; j < 8; ++j) {
        dh[j] = make_uint4(uh[4 * j], uh[4 * j + 1], uh[4 * j + 2], uh[4 * j + 3]);
        dl[j] = make_uint4(ul[4 * j], ul[4 * j + 1], ul[4 * j + 2], ul[4 * j + 3]);
    }
}

// ---------------- kernel 2: per-point GEMMs ----------------
__global__ void yw_kernel(const float* __restrict__ x, const float* __restrict__ W) {
    __shared__ float Wt1[64 * 65];
    __shared__ float Wt3[64 * 65];
    __shared__ float px[8 * 68];

    int tx = threadIdx.x, ty = threadIdx.y;
    int tid = ty * 64 + tx;

    for (int i = tid; i < 64 * 128; i += 512) {
        int c2 = i & 127, o = i >> 7;
        float w = W[i];
        if (c2 < 64) Wt1[c2 * 65 + o] = w;
        else         Wt3[(c2 - 64) * 65 + o] = w;
    }
    __syncthreads();
    for (int i = tid; i < 64 * 64; i += 512) {
        int c = i >> 6, o = i & 63;
        Wt3[c * 65 + o] -= Wt1[c * 65 + o];
    }

    int nbase = blockIdx.x * 64;
    for (int batch = 0; batch < 8; ++batch) {
        __syncthreads();
        {
            int c = tid >> 3, p = tid & 7;
            int nf = nbase + batch * 8 + p;
            int b = nf >> 13, n = nf & (NN - 1);
            px[p * 68 + c] = x[(size_t)b * CC * NN + c * NN + n];
        }
        __syncthreads();
        int nf = nbase + batch * 8 + ty;
        float a1 = 0.0f, a3 = 0.0f;
#pragma unroll
        for (int c = 0; c < 64; ++c) {
            float f = px[ty * 68 + c];
            a1 = fmaf(Wt1[c * 65 + tx], f, a1);
            a3 = fmaf(Wt3[c * 65 + tx], f, a3);
        }
        g_y1[nf * 64 + tx] = a1;
        g_y3[nf * 64 + tx] = a3;
    }
}

// ---------------- kernel 3: kNN, fp16 3-product, 8 warps x 16 rows --------
// 256 threads. Warp w owns query rows 16w..16w+15 (A frags persistent).
// Thread: row q = 16w + (lane&15), col half h = lane>>4 (32 keys/step).
// Pipelined: scan of step t-1 overlaps HMMA of step t. Register top-k.
__global__ void __launch_bounds__(256, 2) knn_mma_kernel() {
    extern __shared__ __align__(128) char smem[];
    u32 sb = smem_u32(smem);

    int tid = threadIdx.x;
    int w = tid >> 5;
    int lane = tid & 31;
    int g = lane >> 2;
    int tig = lane & 3;
    int b = blockIdx.y;
    int qb = blockIdx.x * QT;
    int prow = b * NN;   // row base into g_xhi/g_xlo/g_sqn

    // ---- prologue: cp.async A_hi (into S region), A_lo, B tile 0, csq 0
    {
#pragma unroll
        for (int j = 0; j < 4; ++j) {
            int cid = j * 256 + tid;
            int r = cid >> 3, col = cid & 7;
            cp16(sb + SM_S + r * RS + col * 16, g_xhi + (size_t)(prow + qb + r) * 32 + col * 4);
            cp16(sb + SM_ALO + r * RS + col * 16, g_xlo + (size_t)(prow + qb + r) * 32 + col * 4);
        }
#pragma unroll
        for (int j = 0; j < 2; ++j) {
            int cid = j * 256 + tid;
            int r = cid >> 3, col = cid & 7;
            cp16(sb + SM_B + r * RS + col * 16, g_xhi + (size_t)(prow + r) * 32 + col * 4);
            cp16(sb + SM_B + 9216 + r * RS + col * 16, g_xlo + (size_t)(prow + r) * 32 + col * 4);
        }
        if (tid < 16) cp16(sb + SM_CSQ + tid * 16, g_sqn + prow + tid * 4);
        cp_commit();
        cp_wait0();
        __syncthreads();
    }

    // ---- ldmatrix A_hi fragments (persistent in registers; 16 rows/warp)
    u32 ahi[4][4];
    {
        int r = 16 * w + (lane & 15);
        int byo = (lane >> 4) * 16;
#pragma unroll
        for (int k = 0; k < 4; ++k) {
            u32 addr = sb + SM_S + r * RS + k * 32 + byo;
            ldm4(ahi[k][0], ahi[k][1], ahi[k][2], ahi[k][3], addr);
        }
    }
    __syncthreads();   // all warps done reading A_hi before S is written

    float bestk[KK];
    int besti[KK];
#pragma unroll
    for (int t = 0; t < KK; ++t) { bestk[t] = finf(); besti[t] = 0; }
    float thr = finf();
    u64 kbuf[BUFSZ];   // dynamically indexed -> local memory (by design)
    int cnt = 0;

    const int q = 16 * w + (lane & 15);
    const int h = lane >> 4;
    const int qglob = qb + q;
    const int aml_row = q;
    const int aml_byo = (lane >> 4) * 16;
    const int b_row = ((lane & 16) ? 8 : 0) + (lane & 7);
    const int b_byo = (lane & 8) ? 16 : 0;
    const u64 neg2 = pack2(-2.0f, -2.0f);
    float* S = (float*)(smem + SM_S);

#pragma unroll 1
    for (int t = 0; t < STEPS; ++t) {
        int wb = t & 1;
        int cb = t * CT;
        u32 bbase = sb + SM_B + wb * 18432;

        float c[8][4];
#pragma unroll
        for (int nt = 0; nt < 8; ++nt)
#pragma unroll
            for (int e = 0; e < 4; ++e) c[nt][e] = 0.0f;

        // ---- issue LDSM + MMA for tile t
#pragma unroll
        for (int k = 0; k < 4; ++k) {
            u32 alo[4];
            ldm4(alo[0], alo[1], alo[2], alo[3],
                 sb + SM_ALO + aml_row * RS + k * 32 + aml_byo);
            u32 bh[8][2], bl[8][2];
#pragma unroll
            for (int p = 0; p < 4; ++p) {
                u32 ah = bbase + (16 * p + b_row) * RS + k * 32 + b_byo;
                ldm4(bh[2 * p][0], bh[2 * p][1], bh[2 * p + 1][0], bh[2 * p + 1][1], ah);
                ldm4(bl[2 * p][0], bl[2 * p][1], bl[2 * p + 1][0], bl[2 * p + 1][1], ah + 9216);
            }
#pragma unroll
            for (int nt = 0; nt < 8; ++nt) {
                mma_f16(c[nt], ahi[k][0], ahi[k][1], ahi[k][2], ahi[k][3], bh[nt][0], bh[nt][1]);
                mma_f16(c[nt], ahi[k][0], ahi[k][1], ahi[k][2], ahi[k][3], bl[nt][0], bl[nt][1]);
                mma_f16(c[nt], alo[0], alo[1], alo[2], alo[3], bh[nt][0], bh[nt][1]);
            }
        }

        // ---- prefetch next B tile + csq
        if (t + 1 < STEPS) {
            int cb1 = cb + CT;
            u32 nbase = sb + SM_B + (wb ^ 1) * 18432;
#pragma unroll
            for (int j = 0; j < 2; ++j) {
                int cid = j * 256 + tid;
                int r = cid >> 3, col = cid & 7;
                cp16(nbase + r * RS + col * 16, g_xhi + (size_t)(prow + cb1 + r) * 32 + col * 4);
                cp16(nbase + 9216 + r * RS + col * 16, g_xlo + (size_t)(prow + cb1 + r) * 32 + col * 4);
            }
            if (tid < 16) cp16(sb + SM_CSQ + (wb ^ 1) * 256 + tid * 16, g_sqn + prow + cb1 + tid * 4);
        }
        cp_commit();

        // ---- scan PREVIOUS step's keys (overlaps HMMA of tile t)
        if (t > 0) {
            int pcb = cb - CT;
            u32 ql = (u32)(qglob - pcb) - 32u * (u32)h;
            if (ql < 32u) S[q * 66 + 32 * h + ql] = finf();   // diagonal poison
            const float* Srow = &S[q * 66 + 32 * h];
            int nb0 = pcb + 32 * h;
#pragma unroll 1
            for (int n2 = 0; n2 < 4; ++n2) {
#pragma unroll
                for (int u = 0; u < 4; ++u) {
                    int n = n2 * 8 + u * 2;
                    float2 d = *(const float2*)&Srow[n];
                    if (d.x < thr) {
                        kbuf[cnt] = ((u64)__float_as_uint(d.x) << 32) | (u32)(nb0 + n);
                        ++cnt;
                    }
                    if (d.y < thr) {
                        kbuf[cnt] = ((u64)__float_as_uint(d.y) << 32) | (u32)(nb0 + n + 1);
                        ++cnt;
                    }
                }
                if (__any_sync(0xffffffffu, cnt >= BUFSZ - 8))
                    topk_flush(bestk, besti, thr, kbuf, cnt);
            }
        }
        __syncwarp();   // scan readers done before this warp's key stores

        // ---- store FOLDED KEYS for tile t (first consumer of c)
        {
            const float* csqw = (const float*)(smem + SM_CSQ + wb * 256);
            int rbase = 16 * w + g;
#pragma unroll
            for (int nt = 0; nt < 8; ++nt) {
                int col = 8 * nt + 2 * tig;
                u64 cs = *(const u64*)&csqw[col];
                u64 k01 = cs, k23 = cs;
                fma2(k01, pack2(c[nt][0], c[nt][1]), neg2);
                fma2(k23, pack2(c[nt][2], c[nt][3]), neg2);
                *(u64*)&S[rbase * 66 + col] = k01;
                *(u64*)&S[(rbase + 8) * 66 + col] = k23;
            }
        }

        cp_wait0();
        __syncthreads();
    }

    // ---- epilogue: scan final step's keys
    {
        int pcb = (STEPS - 1) * CT;
        u32 ql = (u32)(qglob - pcb) - 32u * (u32)h;
        if (ql < 32u) S[q * 66 + 32 * h + ql] = finf();
        const float* Srow = &S[q * 66 + 32 * h];
        int nb0 = pcb + 32 * h;
#pragma unroll 1
        for (int n2 = 0; n2 < 4; ++n2) {
#pragma unroll
            for (int u = 0; u < 4; ++u) {
                int n = n2 * 8 + u * 2;
                float2 d = *(const float2*)&Srow[n];
                if (d.x < thr) {
                    kbuf[cnt] = ((u64)__float_as_uint(d.x) << 32) | (u32)(nb0 + n);
                    ++cnt;
                }
                if (d.y < thr) {
                    kbuf[cnt] = ((u64)__float_as_uint(d.y) << 32) | (u32)(nb0 + n + 1);
                    ++cnt;
                }
            }
            if (__any_sync(0xffffffffu, cnt >= BUFSZ - 8))
                topk_flush(bestk, besti, thr, kbuf, cnt);
        }
    }
    topk_flush(bestk, besti, thr, kbuf, cnt);

    int base = ((prow + qglob) * SEGS + h) * KK;
#pragma unroll
    for (int t = 0; t < KK; ++t) {
        g_segk[base + t] = bestk[t];
        g_segi[base + t] = besti[t];
    }
}

// ---------------- kernel 4: merge per-segment top-k ----------------------
__global__ void merge_kernel() {
    int i = blockIdx.x * blockDim.x + threadIdx.x;
    const float* sk = g_segk + (size_t)i * (SEGS * KK);
    const int* si = g_segi + (size_t)i * (SEGS * KK);

    float bestk[KK];
    int besti[KK];
#pragma unroll
    for (int t = 0; t < KK; ++t) { bestk[t] = finf(); besti[t] = 0; }
    float thr = finf();

#pragma unroll 1
    for (int t = 0; t < SEGS * KK; ++t) {
        float kk = sk[t];
        if (kk < thr) topk_insert(bestk, besti, thr, kk, si[t]);
    }
    int* op = g_idx + (size_t)i * KK;
#pragma unroll
    for (int t = 0; t < KK; ++t) op[t] = besti[t];
}

// ---------------- kernel 5: gather + minmax + BN partials ----------------
__global__ void gather_kernel() {
    __shared__ float ss[64], ss2[64];
    int o = threadIdx.x;
    int p = threadIdx.y;
    int nf = blockIdx.x * 8 + p;
    int b = nf >> 13;

    float y3v = g_y3[nf * 64 + o];
    const int* ip = g_idx + (size_t)nf * KK;

    float vmax = -finf();
    float vmin = finf();
    float s = 0.0f, s2 = 0.0f;
#pragma unroll
    for (int kk = 0; kk < KK; ++kk) {
        int m = ip[kk];
        float v = g_y1[((b << 13) + m) * 64 + o] + y3v;
        vmax = fmaxf(vmax, v);
        vmin = fminf(vmin, v);
        s += v;
        s2 = fmaf(v, v, s2);
    }
    g_maxh[nf * 64 + o] = vmax;
    g_minh[nf * 64 + o] = vmin;

    if (p == 0) { ss[o] = 0.0f; ss2[o] = 0.0f; }
    __syncthreads();
    atomicAdd(&ss[o], s);
    atomicAdd(&ss2[o], s2);
    __syncthreads();
    if (p == 0) {
        atomicAdd(&g_sum[o], ss[o]);
        atomicAdd(&g_sumsq[o], ss2[o]);
    }
}

// ---------------- kernel 6: finalize BN stats ----------------
__global__ void stats_kernel(const float* __restrict__ gamma,
                             const float* __restrict__ beta) {
    int o = threadIdx.x;
    float cnt = (float)CNT_TOT;
    float mean = g_sum[o] / cnt;
    float var = g_sumsq[o] / cnt - mean * mean;
    float invstd = rsqrtf(var + 1e-5f);
    float sc = gamma[o] * invstd;
    g_scale[o] = sc;
    g_shift[o] = beta[o] - mean * sc;
}

// ---------------- kernel 7: output ----------------
__global__ void out_kernel(float* __restrict__ out) {
    int i = blockIdx.x * blockDim.x + threadIdx.x;
    int n = i & (NN - 1);
    int bo = i >> 13;
    int o = bo & 63;
    int b = bo >> 6;
    float sc = g_scale[o];
    float sh = g_shift[o];
    int nf = (b << 13) + n;
    float h = (sc >= 0.0f) ? g_maxh[nf * 64 + o] : g_minh[nf * 64 + o];
    out[i] = fmaxf(fmaf(h, sc, sh), 0.0f);
}

// ---------------- launch ----------------
extern "C" void kernel_launch(void* const* d_in, const int* in_sizes, int n_in,
                              void* d_out, int out_size) {
    const float* x = (const float*)d_in[0];
    const float* W = (const float*)d_in[1];
    const float* gamma = (const float*)d_in[2];
    const float* beta = (const float*)d_in[3];
    float* out = (float*)d_out;

    cudaFuncSetAttribute(knn_mma_kernel, cudaFuncAttributeMaxDynamicSharedMemorySize, SM_BYTES);

    init_stats_kernel<<<1, 64>>>();
    xhl_kernel<<<(BB * NN) / 256, 256>>>(x);
    yw_kernel<<<(BB * NN) / 64, dim3(64, 8)>>>(x, W);
    knn_mma_kernel<<<dim3(NN / QT, BB), 256, SM_BYTES>>>();
    merge_kernel<<<(BB * NN) / 128, 128>>>();
    gather_kernel<<<(BB * NN) / 8, dim3(64, 8)>>>();
    stats_kernel<<<1, 64>>>(gamma, beta);
    out_kernel<<<(BB * CO * NN) / 256, 256>>>(out);
}

// round 17
// speedup vs baseline: 1.4031x; 1.4031x over previous
#include <cuda_runtime.h>
#include <cuda_fp16.h>

#define BB 4
#define CC 64
#define NN 8192
#define KK 20
#define CO 64
#define BUFSZ 24
#define CNT_TOT (BB * NN * KK)

#define QT 128          // queries per CTA
#define CT 64           // candidates per step
#define STEPS (NN / CT) // 128
#define RS 144          // smem row stride bytes (128B data + 16B pad)

typedef unsigned long long u64;
typedef unsigned int u32;

// ---------------- device scratch ----------------
__device__ float g_sqn[BB * NN];
__device__ __align__(16) u32 g_xhi[BB * NN * 32];   // f16x2 [point][64ch]
__device__ __align__(16) u32 g_xlo[BB * NN * 32];
__device__ float g_y1[BB * NN * CO];
__device__ float g_y3[BB * NN * CO];
__device__ int   g_idx[BB * NN * KK];
__device__ float g_maxh[BB * NN * CO];
__device__ float g_minh[BB * NN * CO];
__device__ float g_sum[CO];
__device__ float g_sumsq[CO];
__device__ float g_scale[CO];
__device__ float g_shift[CO];

__device__ __forceinline__ float finf() { return __int_as_float(0x7f800000); }

// ---------------- smem layout (bytes) ----------------
// S region (128*66*4 = 33792) doubles as A_hi staging (needs 128*144=18432)
#define SM_S    0
#define SM_ALO  33792
#define SM_B    (33792 + 18432)                  // 52224; buffer w at +w*18432 (hi|lo)
#define SM_CSQ  (SM_B + 2 * 18432)               // 89088; buffer w at +w*256
#define SM_BYTES (SM_CSQ + 512)                  // 89600

// ---------------- PTX helpers ----------------
__device__ __forceinline__ u32 smem_u32(const void* p) {
    u32 a;
    asm("{ .reg .u64 t; cvta.to.shared.u64 t, %1; cvt.u32.u64 %0, t; }" : "=r"(a) : "l"(p));
    return a;
}
__device__ __forceinline__ void ldm4(u32& r0, u32& r1, u32& r2, u32& r3, u32 addr) {
    asm volatile("ldmatrix.sync.aligned.m8n8.x4.shared.b16 {%0,%1,%2,%3}, [%4];"
                 : "=r"(r0), "=r"(r1), "=r"(r2), "=r"(r3) : "r"(addr));
}
__device__ __forceinline__ void mma_f16(float (&c)[4], const u32 a0, const u32 a1,
                                        const u32 a2, const u32 a3,
                                        const u32 b0, const u32 b1) {
    asm volatile(
        "mma.sync.aligned.m16n8k16.row.col.f32.f16.f16.f32 "
        "{%0,%1,%2,%3}, {%4,%5,%6,%7}, {%8,%9}, {%0,%1,%2,%3};"
        : "+f"(c[0]), "+f"(c[1]), "+f"(c[2]), "+f"(c[3])
        : "r"(a0), "r"(a1), "r"(a2), "r"(a3), "r"(b0), "r"(b1));
}
__device__ __forceinline__ void cp16(u32 dst, const void* src) {
    asm volatile("cp.async.cg.shared.global [%0], [%1], 16;" :: "r"(dst), "l"(src));
}
__device__ __forceinline__ void cp_commit() { asm volatile("cp.async.commit_group;" ::: "memory"); }
__device__ __forceinline__ void cp_wait0()  { asm volatile("cp.async.wait_group 0;" ::: "memory"); }

// packed f32x2: acc = a*b + acc (in-place, no MOV tax)
__device__ __forceinline__ void fma2(u64& acc, u64 a, u64 b) {
    asm("fma.rn.f32x2 %0, %1, %2, %0;" : "+l"(acc) : "l"(a), "l"(b));
}
__device__ __forceinline__ u64 pack2(float x, float y) {
    u64 r;
    asm("mov.b64 %0, {%1,%2};" : "=l"(r) : "f"(x), "f"(y));
    return r;
}

// ---------------- top-k helpers (registers only; static indices) --------
__device__ __forceinline__ void topk_insert(float (&bk)[KK], int (&bi)[KK],
                                            float& thr, float key, int jg) {
    bool done = false;
#pragma unroll
    for (int t = 0; t < KK; ++t)
        if (!done && bk[t] == thr) { bk[t] = key; bi[t] = jg; done = true; }
    float m = bk[0];
#pragma unroll
    for (int t = 1; t < KK; ++t) m = fmaxf(m, bk[t]);
    thr = m;
}
__device__ __forceinline__ void topk_flush(float (&bk)[KK], int (&bi)[KK], float& thr,
                                           u64* buf, int& cnt) {
#pragma unroll 1
    for (int i = 0; i < cnt; ++i) {
        u64 e = buf[i];
        float kk = __uint_as_float((u32)(e >> 32));
        if (kk < thr) topk_insert(bk, bi, thr, kk, (int)(u32)e);
    }
    cnt = 0;
}

// ---------------- kernel 0 ----------------
__global__ void init_stats_kernel() {
    int o = threadIdx.x;
    g_sum[o] = 0.0f;
    g_sumsq[o] = 0.0f;
}

// ---------------- kernel 1: fp16 hi/lo split + squared norms -------------
__global__ void xhl_kernel(const float* __restrict__ x) {
    int i = blockIdx.x * 256 + threadIdx.x;
    int b = i >> 13;
    const float* xb = x + (size_t)b * CC * NN + (i & (NN - 1));
    u32 uh[32], ul[32];
    float s = 0.0f;
#pragma unroll
    for (int c2 = 0; c2 < 32; ++c2) {
        float v0 = xb[(2 * c2) * NN];
        float v1 = xb[(2 * c2 + 1) * NN];
        s = fmaf(v0, v0, s);
        s = fmaf(v1, v1, s);
        __half h0 = __float2half_rn(v0);
        __half h1 = __float2half_rn(v1);
        __half l0 = __float2half_rn(v0 - __half2float(h0));
        __half l1 = __float2half_rn(v1 - __half2float(h1));
        uh[c2] = (u32)__half_as_ushort(h0) | ((u32)__half_as_ushort(h1) << 16);
        ul[c2] = (u32)__half_as_ushort(l0) | ((u32)__half_as_ushort(l1) << 16);
    }
    g_sqn[i] = s;
    uint4* dh = (uint4*)(g_xhi + (size_t)i * 32);
    uint4* dl = (uint4*)(g_xlo + (size_t)i * 32);
#pragma unroll
    for (int j = 0; j < 8; ++j) {
        dh[j] = make_uint4(uh[4 * j], uh[4 * j + 1], uh[4 * j + 2], uh[4 * j + 3]);
        dl[j] = make_uint4(ul[4 * j], ul[4 * j + 1], ul[4 * j + 2], ul[4 * j + 3]);
    }
}

// ---------------- kernel 2: per-point GEMMs ----------------
__global__ void yw_kernel(const float* __restrict__ x, const float* __restrict__ W) {
    __shared__ float Wt1[64 * 65];
    __shared__ float Wt3[64 * 65];
    __shared__ float px[8 * 68];

    int tx = threadIdx.x, ty = threadIdx.y;
    int tid = ty * 64 + tx;

    for (int i = tid; i < 64 * 128; i += 512) {
        int c2 = i & 127, o = i >> 7;
        float w = W[i];
        if (c2 < 64) Wt1[c2 * 65 + o] = w;
        else         Wt3[(c2 - 64) * 65 + o] = w;
    }
    __syncthreads();
    for (int i = tid; i < 64 * 64; i += 512) {
        int c = i >> 6, o = i & 63;
        Wt3[c * 65 + o] -= Wt1[c * 65 + o];
    }

    int nbase = blockIdx.x * 64;
    for (int batch = 0; batch < 8; ++batch) {
        __syncthreads();
        {
            int c = tid >> 3, p = tid & 7;
            int nf = nbase + batch * 8 + p;
            int b = nf >> 13, n = nf & (NN - 1);
            px[p * 68 + c] = x[(size_t)b * CC * NN + c * NN + n];
        }
        __syncthreads();
        int nf = nbase + batch * 8 + ty;
        float a1 = 0.0f, a3 = 0.0f;
#pragma unroll
        for (int c = 0; c < 64; ++c) {
            float f = px[ty * 68 + c];
            a1 = fmaf(Wt1[c * 65 + tx], f, a1);
            a3 = fmaf(Wt3[c * 65 + tx], f, a3);
        }
        g_y1[nf * 64 + tx] = a1;
        g_y3[nf * 64 + tx] = a3;
    }
}

// ---------------- kernel 3: kNN via mma.sync fp16 (3-product split) ------
// R15 skeleton (pipelined scan); votes every 16 candidates (BUFSZ 24).
__global__ void __launch_bounds__(128, 2) knn_mma_kernel() {
    extern __shared__ __align__(128) char smem[];
    u32 sb = smem_u32(smem);

    int tid = threadIdx.x;
    int w = tid >> 5;
    int lane = tid & 31;
    int g = lane >> 2;
    int tig = lane & 3;
    int b = blockIdx.y;
    int qb = blockIdx.x * QT;
    int prow = b * NN;   // row base into g_xhi/g_xlo/g_sqn

    // ---- prologue: cp.async A_hi (into S region), A_lo, B tile 0, csq 0
    {
#pragma unroll
        for (int j = 0; j < 8; ++j) {
            int cid = j * 128 + tid;
            int r = cid >> 3, col = cid & 7;
            cp16(sb + SM_S + r * RS + col * 16, g_xhi + (size_t)(prow + qb + r) * 32 + col * 4);
            cp16(sb + SM_ALO + r * RS + col * 16, g_xlo + (size_t)(prow + qb + r) * 32 + col * 4);
        }
#pragma unroll
        for (int j = 0; j < 4; ++j) {
            int cid = j * 128 + tid;
            int r = cid >> 3, col = cid & 7;
            cp16(sb + SM_B + r * RS + col * 16, g_xhi + (size_t)(prow + r) * 32 + col * 4);
            cp16(sb + SM_B + 9216 + r * RS + col * 16, g_xlo + (size_t)(prow + r) * 32 + col * 4);
        }
        if (tid < 16) cp16(sb + SM_CSQ + tid * 16, g_sqn + prow + tid * 4);
        cp_commit();
        cp_wait0();
        __syncthreads();
    }

    // ---- ldmatrix A_hi fragments (persistent in registers)
    u32 ahi[2][4][4];
    {
        int r = 32 * w + (lane & 15);
        int byo = (lane >> 4) * 16;
#pragma unroll
        for (int mt = 0; mt < 2; ++mt)
#pragma unroll
            for (int k = 0; k < 4; ++k) {
                u32 addr = sb + SM_S + (r + 16 * mt) * RS + k * 32 + byo;
                ldm4(ahi[mt][k][0], ahi[mt][k][1], ahi[mt][k][2], ahi[mt][k][3], addr);
            }
    }
    __syncthreads();   // all warps done reading A_hi before S is written

    float bestk[KK];
    int besti[KK];
#pragma unroll
    for (int t = 0; t < KK; ++t) { bestk[t] = finf(); besti[t] = 0; }
    float thr = finf();
    u64 kbuf[BUFSZ];
    int cnt = 0;

    const int aml_row = 32 * w + (lane & 15);
    const int aml_byo = (lane >> 4) * 16;
    const int b_row = ((lane & 16) ? 8 : 0) + (lane & 7);
    const int b_byo = (lane & 8) ? 16 : 0;
    const u64 neg2 = pack2(-2.0f, -2.0f);
    float* S = (float*)(smem + SM_S);

#pragma unroll 1
    for (int t = 0; t < STEPS; ++t) {
        int wb = t & 1;
        int cb = t * CT;
        u32 bbase = sb + SM_B + wb * 18432;

        float c[2][8][4];
#pragma unroll
        for (int mt = 0; mt < 2; ++mt)
#pragma unroll
            for (int nt = 0; nt < 8; ++nt)
#pragma unroll
                for (int e = 0; e < 4; ++e) c[mt][nt][e] = 0.0f;

        // ---- issue LDSM + MMA for tile t
#pragma unroll
        for (int k = 0; k < 4; ++k) {
            u32 alo[2][4];
#pragma unroll
            for (int mt = 0; mt < 2; ++mt)
                ldm4(alo[mt][0], alo[mt][1], alo[mt][2], alo[mt][3],
                     sb + SM_ALO + (aml_row + 16 * mt) * RS + k * 32 + aml_byo);
            u32 bh[8][2], bl[8][2];
#pragma unroll
            for (int p = 0; p < 4; ++p) {
                u32 ah = bbase + (16 * p + b_row) * RS + k * 32 + b_byo;
                ldm4(bh[2 * p][0], bh[2 * p][1], bh[2 * p + 1][0], bh[2 * p + 1][1], ah);
                ldm4(bl[2 * p][0], bl[2 * p][1], bl[2 * p + 1][0], bl[2 * p + 1][1], ah + 9216);
            }
#pragma unroll
            for (int mt = 0; mt < 2; ++mt)
#pragma unroll
                for (int nt = 0; nt < 8; ++nt) {
                    mma_f16(c[mt][nt], ahi[mt][k][0], ahi[mt][k][1], ahi[mt][k][2], ahi[mt][k][3],
                            bh[nt][0], bh[nt][1]);
                    mma_f16(c[mt][nt], ahi[mt][k][0], ahi[mt][k][1], ahi[mt][k][2], ahi[mt][k][3],
                            bl[nt][0], bl[nt][1]);
                    mma_f16(c[mt][nt], alo[mt][0], alo[mt][1], alo[mt][2], alo[mt][3],
                            bh[nt][0], bh[nt][1]);
                }
        }

        // ---- prefetch next B tile + csq
        if (t + 1 < STEPS) {
            int cb1 = cb + CT;
            u32 nbase = sb + SM_B + (wb ^ 1) * 18432;
#pragma unroll
            for (int j = 0; j < 4; ++j) {
                int cid = j * 128 + tid;
                int r = cid >> 3, col = cid & 7;
                cp16(nbase + r * RS + col * 16, g_xhi + (size_t)(prow + cb1 + r) * 32 + col * 4);
                cp16(nbase + 9216 + r * RS + col * 16, g_xlo + (size_t)(prow + cb1 + r) * 32 + col * 4);
            }
            if (tid < 16) cp16(sb + SM_CSQ + (wb ^ 1) * 256 + tid * 16, g_sqn + prow + cb1 + tid * 4);
        }
        cp_commit();

        // ---- scan PREVIOUS step's keys (overlaps HMMA of tile t)
        if (t > 0) {
            int pcb = cb - CT;
            u32 qloc = (u32)(qb + tid - pcb);
            if (qloc < (u32)CT) S[tid * 66 + qloc] = finf();   // diagonal poison
            const float* Srow = &S[tid * 66];
#pragma unroll 1
            for (int n4 = 0; n4 < 4; ++n4) {
#pragma unroll
                for (int u = 0; u < 8; ++u) {
                    int n = n4 * 16 + u * 2;
                    float2 d = *(const float2*)&Srow[n];
                    if (d.x < thr) {
                        kbuf[cnt] = ((u64)__float_as_uint(d.x) << 32) | (u32)(pcb + n);
                        ++cnt;
                    }
                    if (d.y < thr) {
                        kbuf[cnt] = ((u64)__float_as_uint(d.y) << 32) | (u32)(pcb + n + 1);
                        ++cnt;
                    }
                }
                if (__any_sync(0xffffffffu, cnt >= BUFSZ - 16))
                    topk_flush(bestk, besti, thr, kbuf, cnt);
            }
        }
        __syncwarp();   // scan readers done before this warp's key stores

        // ---- store FOLDED KEYS for tile t (first consumer of c => HMMA wait)
        {
            const float* csqw = (const float*)(smem + SM_CSQ + wb * 256);
#pragma unroll
            for (int nt = 0; nt < 8; ++nt) {
                int col = 8 * nt + 2 * tig;
                u64 cs = *(const u64*)&csqw[col];
#pragma unroll
                for (int mt = 0; mt < 2; ++mt) {
                    int rbase = 32 * w + 16 * mt + g;
                    u64 k01 = cs, k23 = cs;
                    fma2(k01, pack2(c[mt][nt][0], c[mt][nt][1]), neg2);
                    fma2(k23, pack2(c[mt][nt][2], c[mt][nt][3]), neg2);
                    *(u64*)&S[rbase * 66 + col] = k01;
                    *(u64*)&S[(rbase + 8) * 66 + col] = k23;
                }
            }
        }

        cp_wait0();
        __syncthreads();
    }

    // ---- epilogue: scan final step's keys
    {
        int pcb = (STEPS - 1) * CT;
        u32 qloc = (u32)(qb + tid - pcb);
        if (qloc < (u32)CT) S[tid * 66 + qloc] = finf();
        const float* Srow = &S[tid * 66];
#pragma unroll 1
        for (int n4 = 0; n4 < 4; ++n4) {
#pragma unroll
            for (int u = 0; u < 8; ++u) {
                int n = n4 * 16 + u * 2;
                float2 d = *(const float2*)&Srow[n];
                if (d.x < thr) {
                    kbuf[cnt] = ((u64)__float_as_uint(d.x) << 32) | (u32)(pcb + n);
                    ++cnt;
                }
                if (d.y < thr) {
                    kbuf[cnt] = ((u64)__float_as_uint(d.y) << 32) | (u32)(pcb + n + 1);
                    ++cnt;
                }
            }
            if (__any_sync(0xffffffffu, cnt >= BUFSZ - 16))
                topk_flush(bestk, besti, thr, kbuf, cnt);
        }
    }
    topk_flush(bestk, besti, thr, kbuf, cnt);

    int* op = g_idx + (size_t)(prow + qb + tid) * KK;
#pragma unroll
    for (int t = 0; t < KK; ++t) op[t] = besti[t];
}

// ---------------- kernel 5: gather + minmax + BN partials ----------------
__global__ void gather_kernel() {
    __shared__ float ss[64], ss2[64];
    int o = threadIdx.x;
    int p = threadIdx.y;
    int nf = blockIdx.x * 8 + p;
    int b = nf >> 13;

    float y3v = g_y3[nf * 64 + o];
    const int* ip = g_idx + (size_t)nf * KK;

    float vmax = -finf();
    float vmin = finf();
    float s = 0.0f, s2 = 0.0f;
#pragma unroll
    for (int kk = 0; kk < KK; ++kk) {
        int m = ip[kk];
        float v = g_y1[((b << 13) + m) * 64 + o] + y3v;
        vmax = fmaxf(vmax, v);
        vmin = fminf(vmin, v);
        s += v;
        s2 = fmaf(v, v, s2);
    }
    g_maxh[nf * 64 + o] = vmax;
    g_minh[nf * 64 + o] = vmin;

    if (p == 0) { ss[o] = 0.0f; ss2[o] = 0.0f; }
    __syncthreads();
    atomicAdd(&ss[o], s);
    atomicAdd(&ss2[o], s2);
    __syncthreads();
    if (p == 0) {
        atomicAdd(&g_sum[o], ss[o]);
        atomicAdd(&g_sumsq[o], ss2[o]);
    }
}

// ---------------- kernel 6: finalize BN stats ----------------
__global__ void stats_kernel(const float* __restrict__ gamma,
                             const float* __restrict__ beta) {
    int o = threadIdx.x;
    float cnt = (float)CNT_TOT;
    float mean = g_sum[o] / cnt;
    float var = g_sumsq[o] / cnt - mean * mean;
    float invstd = rsqrtf(var + 1e-5f);
    float sc = gamma[o] * invstd;
    g_scale[o] = sc;
    g_shift[o] = beta[o] - mean * sc;
}

// ---------------- kernel 7: output ----------------
__global__ void out_kernel(float* __restrict__ out) {
    int i = blockIdx.x * blockDim.x + threadIdx.x;
    int n = i & (NN - 1);
    int bo = i >> 13;
    int o = bo & 63;
    int b = bo >> 6;
    float sc = g_scale[o];
    float sh = g_shift[o];
    int nf = (b << 13) + n;
    float h = (sc >= 0.0f) ? g_maxh[nf * 64 + o] : g_minh[nf * 64 + o];
    out[i] = fmaxf(fmaf(h, sc, sh), 0.0f);
}

// ---------------- launch ----------------
extern "C" void kernel_launch(void* const* d_in, const int* in_sizes, int n_in,
                              void* d_out, int out_size) {
    const float* x = (const float*)d_in[0];
    const float* W = (const float*)d_in[1];
    const float* gamma = (const float*)d_in[2];
    const float* beta = (const float*)d_in[3];
    float* out = (float*)d_out;

    cudaFuncSetAttribute(knn_mma_kernel, cudaFuncAttributeMaxDynamicSharedMemorySize, SM_BYTES);

    init_stats_kernel<<<1, 64>>>();
    xhl_kernel<<<(BB * NN) / 256, 256>>>(x);
    yw_kernel<<<(BB * NN) / 64, dim3(64, 8)>>>(x, W);
    knn_mma_kernel<<<dim3(NN / QT, BB), 128, SM_BYTES>>>();
    gather_kernel<<<(BB * NN) / 8, dim3(64, 8)>>>();
    stats_kernel<<<1, 64>>>(gamma, beta);
    out_kernel<<<(BB * CO * NN) / 256, 256>>>(out);
}